// round 8
// baseline (speedup 1.0000x reference)
#include <cuda_runtime.h>
#include <cuda_fp16.h>
#include <cstdint>

// TwoBranchDH_SFNN, R7: warp-specialized pipeline.
// grid=128 (block per batch), 1024 threads (32 warps):
//   warps  0-15 ("compute"): recurrence + ysum, thread <-> channel (h = tid)
//   warps 16-31 ("mma"):     x staging + ldmatrix + HMMA + dot STS
// One __syncthreads per 16-timestep stage; dots / y / x double-buffered.

namespace {

constexpr int B_SZ  = 128;
constexpr int T_SZ  = 2048;
constexpr int DIN   = 40;
constexpr int KHALF = 20;
constexpr int THREADS = 1024;
constexpr int ST      = 16;             // timesteps per stage
constexpr int NSTAGES = T_SZ / ST;      // 128

// smem geometry (32-bit words)
constexpr int TCW  = 513 * 4;           // words per tc-slab (4 t x 512 ch padded)
constexpr int BRW  = 4 * TCW;           // per-branch dot words
constexpr int DOTW = 2 * BRW;           // both branches (one buffer)
constexpr int YW   = 520;               // y row stride (words)
constexpr int YTOT = 16 * YW;           // one y buffer
constexpr int XW   = 16 * 64;           // halves per x buffer
constexpr int SMEM_BYTES = (2 * DOTW + 2 * YTOT) * 4 + 2 * XW * 2;  // 201984 B

typedef unsigned long long u64;
typedef uint32_t u32;

__device__ __forceinline__ u32 smem_u32(const void* p) {
    u32 a;
    asm("{ .reg .u64 t; cvta.to.shared.u64 t, %1; cvt.u32.u64 %0, t; }"
        : "=r"(a) : "l"(p));
    return a;
}
__device__ __forceinline__ u64 pkf(float lo, float hi) {
    u64 r; asm("mov.b64 %0, {%1, %2};" : "=l"(r) : "f"(lo), "f"(hi)); return r;
}
__device__ __forceinline__ float2 unpk(u64 v) {
    float2 r; asm("mov.b64 {%0, %1}, %2;" : "=f"(r.x), "=f"(r.y) : "l"(v)); return r;
}
__device__ __forceinline__ u64 fma2(u64 a, u64 b, u64 c) {
    u64 d; asm("fma.rn.f32x2 %0, %1, %2, %3;" : "=l"(d) : "l"(a), "l"(b), "l"(c)); return d;
}

__device__ __forceinline__ void ldmat4(u32* r, u32 addr) {
    asm volatile("ldmatrix.sync.aligned.m8n8.x4.shared.b16 {%0,%1,%2,%3}, [%4];"
                 : "=r"(r[0]), "=r"(r[1]), "=r"(r[2]), "=r"(r[3]) : "r"(addr));
}
__device__ __forceinline__ void mma16816(float& d0, float& d1, float& d2, float& d3,
                                         const u32* a, u32 b0, u32 b1) {
    asm volatile("mma.sync.aligned.m16n8k16.row.col.f32.f16.f16.f32 "
                 "{%0,%1,%2,%3}, {%4,%5,%6,%7}, {%8,%9}, {%0,%1,%2,%3};"
                 : "+f"(d0), "+f"(d1), "+f"(d2), "+f"(d3)
                 : "r"(a[0]), "r"(a[1]), "r"(a[2]), "r"(a[3]), "r"(b0), "r"(b1));
}
__device__ __forceinline__ float sigf(float v) { return 1.0f / (1.0f + expf(-v)); }
__device__ __forceinline__ u32 packh(float a, float b) {
    __half2 h = __floats2half2_rn(a, b);
    return *reinterpret_cast<u32*>(&h);
}

__global__ void __launch_bounds__(THREADS, 1)
sfnn_ws_kernel(const float* __restrict__ x,
               const float* __restrict__ W1, const float* __restrict__ b1,
               const float* __restrict__ W2, const float* __restrict__ b2,
               const float* __restrict__ Wo, const float* __restrict__ bo,
               const float* __restrict__ tau_m, const float* __restrict__ tau_n1,
               const float* __restrict__ tau_n2, float* __restrict__ out) {
    extern __shared__ __align__(16) float sm[];
    float* dotsm = sm;                                   // 2*DOTW words
    float* ysm   = sm + 2 * DOTW;                        // 2*YTOT words
    __half* xsm  = reinterpret_cast<__half*>(sm + 2 * DOTW + 2 * YTOT);

    const int tid  = threadIdx.x;
    const int lane = tid & 31;
    const int wid  = tid >> 5;
    const int b    = blockIdx.x;
    const bool is_mma = (wid >= 16);

    const float* xg = x + (size_t)b * T_SZ * DIN;
    const u32 xbase = smem_u32(xsm);

    // ================= compute-role constants =================
    u64 Bp = 0, Gp = 0, GBp = 0;
    float av = 0.f, amg = 0.f, wo = 0.f, bov = 0.f;
    if (!is_mma) {
        const int h = tid;
        const float b1v = sigf(tau_n1[h]), b2v = sigf(tau_n2[h]);
        av  = sigf(tau_m[h]);
        Bp  = pkf(b1v, b2v);
        Gp  = pkf(1.f - b1v, 1.f - b2v);
        GBp = pkf((1.f - b1v) * b1[h], (1.f - b2v) * b2[h]);
        amg = 1.f - av;
        wo  = Wo[h];
        bov = bo[0];
    }

    // ================= mma-role constants =================
    const int wid2 = wid - 16;
    const int wbr  = (wid2 >> 3) & 1;           // branch
    const int wb   = (wid2 & 7) * 64;           // channel base
    u32 BF[8][2][2];
    if (is_mma) {
        const float* Ws = wbr ? W2 : W1;
        const int chl = lane >> 2;
        const int kg  = 2 * (lane & 3);
#pragma unroll
        for (int nt = 0; nt < 8; nt++) {
            const int ch = wb + nt * 8 + chl;
#pragma unroll
            for (int kt = 0; kt < 2; kt++) {
                const int k0 = kt * 16 + kg;
                const float v0 = (k0     < KHALF) ? Ws[ch * KHALF + k0    ] : 0.f;
                const float v1 = (k0 + 1 < KHALF) ? Ws[ch * KHALF + k0 + 1] : 0.f;
                const float v2 = (k0 + 8 < KHALF) ? Ws[ch * KHALF + k0 + 8] : 0.f;
                const float v3 = (k0 + 9 < KHALF) ? Ws[ch * KHALF + k0 + 9] : 0.f;
                BF[nt][kt][0] = packh(v0, v1);
                BF[nt][kt][1] = packh(v2, v3);
            }
        }
    }

    // x staging (mma threads): 2 slots of 1024 per thread, direct LDG->STS
    const int tid2 = tid & 511;
    auto stage_x = [&](int s) {
        const int buf = s & 1;
#pragma unroll
        for (int i = 0; i < 2; i++) {
            const int sl = tid2 + i * 512;
            const int t = sl >> 6, kk = sl & 63, br = kk >> 5, k = kk & 31;
            const float v = (k < KHALF)
                ? xg[(size_t)s * (ST * DIN) + t * DIN + br * KHALF + k] : 0.f;
            xsm[buf * XW + t * 64 + kk] = __float2half_rn(v);
        }
    };

    // lane constants for MMA dot store
    const int tlo  = lane >> 2;
    const int tc0  = tlo >> 2;
    const int toff = tlo & 3;
    const int chl2 = 2 * (lane & 3);

    auto mma_stage = [&](int s) {
        const int buf = s & 1;
        u32 A[2][4];
#pragma unroll
        for (int kt = 0; kt < 2; kt++) {
            const u32 addr = xbase + (u32)buf * (XW * 2)
                           + (u32)(lane & 15) * 128
                           + (u32)(wbr * 32 + kt * 16 + ((lane >> 4) << 3)) * 2;
            ldmat4(A[kt], addr);
        }
        const int dB = buf * DOTW + wbr * BRW;
#pragma unroll
        for (int nt = 0; nt < 8; nt++) {
            float d0 = 0.f, d1 = 0.f, d2 = 0.f, d3 = 0.f;
            mma16816(d0, d1, d2, d3, A[0], BF[nt][0][0], BF[nt][0][1]);
            mma16816(d0, d1, d2, d3, A[1], BF[nt][1][0], BF[nt][1][1]);
            const int ch = wb + nt * 8 + chl2;
            const int w0 = dB + tc0 * TCW + ch * 4 + toff;
            dotsm[w0]               = d0;   // (t=tlo,   ch)
            dotsm[w0 + 4]           = d1;   // (t=tlo,   ch+1)
            dotsm[w0 + 2 * TCW]     = d2;   // (t=tlo+8, ch)
            dotsm[w0 + 2 * TCW + 4] = d3;   // (t=tlo+8, ch+1)
        }
    };

    auto ysum = [&](int s) {
        const float4* yr = reinterpret_cast<const float4*>(
            ysm + (s & 1) * YTOT + wid * YW);
        float acc = 0.f;
#pragma unroll
        for (int c = 0; c < 4; c++) {
            const float4 v = yr[lane + c * 32];
            acc += (v.x + v.y) + (v.z + v.w);
        }
#pragma unroll
        for (int off = 16; off; off >>= 1)
            acc += __shfl_xor_sync(0xFFFFFFFFu, acc, off);
        if (lane == 0)
            out[(size_t)b * T_SZ + s * ST + wid] =
                1.f / (1.f + __expf(-(acc + bov)));
    };

    u64 d12 = 0ull;
    float mem = 0.f;

    // ---- prolog: MMA warps stage x(0), x(1); first MMA ----
    if (is_mma) { stage_x(0); stage_x(1); }
    __syncthreads();
    if (is_mma) mma_stage(0);

    // ---- main loop: ONE barrier per stage ----
    for (int s = 0; s < NSTAGES; s++) {
        __syncthreads();   // dots(s), y(s-1), xbuf(s+1) visible

        if (is_mma) {
            if (s + 1 < NSTAGES) mma_stage(s + 1);
            if (s + 2 < NSTAGES) stage_x(s + 2);
        } else {
            if (s > 0) ysum(s - 1);
            // recurrence(s): reads dot buffer s&1, writes y buffer s&1
            const int dB = (s & 1) * DOTW;
            float* yb = ysm + (s & 1) * YTOT;
            const int ch4 = tid * 4;
#pragma unroll
            for (int tc = 0; tc < 4; tc++) {
                const float4 i1 = *reinterpret_cast<const float4*>(
                    dotsm + dB + tc * TCW + ch4);
                const float4 i2 = *reinterpret_cast<const float4*>(
                    dotsm + dB + BRW + tc * TCW + ch4);
                const float i1a[4] = {i1.x, i1.y, i1.z, i1.w};
                const float i2a[4] = {i2.x, i2.y, i2.z, i2.w};
#pragma unroll
                for (int j = 0; j < 4; j++) {
                    d12 = fma2(Bp, d12, fma2(Gp, pkf(i1a[j], i2a[j]), GBp));
                    const float2 dd = unpk(d12);
                    mem = __fmaf_rn(av, mem, amg * (dd.x + dd.y));
                    yb[(tc * 4 + j) * YW + tid] = wo * mem;
                }
            }
        }
    }

    __syncthreads();
    if (!is_mma) ysum(NSTAGES - 1);
}

}  // namespace

extern "C" void kernel_launch(void* const* d_in, const int* in_sizes, int n_in,
                              void* d_out, int out_size) {
    const float* x      = (const float*)d_in[0];
    const float* W1     = (const float*)d_in[1];
    const float* b1     = (const float*)d_in[2];
    const float* W2     = (const float*)d_in[3];
    const float* b2     = (const float*)d_in[4];
    const float* Wo     = (const float*)d_in[5];
    const float* bo     = (const float*)d_in[6];
    const float* tau_m  = (const float*)d_in[7];
    const float* tau_n1 = (const float*)d_in[8];
    const float* tau_n2 = (const float*)d_in[9];
    float* out = (float*)d_out;

    cudaFuncSetAttribute(sfnn_ws_kernel,
                         cudaFuncAttributeMaxDynamicSharedMemorySize, SMEM_BYTES);
    sfnn_ws_kernel<<<B_SZ, THREADS, SMEM_BYTES>>>(x, W1, b1, W2, b2, Wo, bo,
                                                  tau_m, tau_n1, tau_n2, out);
}